// round 10
// baseline (speedup 1.0000x reference)
#include <cuda_runtime.h>
#include <cstdint>

// ---------------------------------------------------------------------------
// DiverseRegDCConv2d: per-sample dynamically-generated 3x3 conv.
//   wgen[b,o,c,kh,kw] = sum_n se[b,n] * weight[(o*C+c)*9+kh*3+kw, n]
//   out[b,o,h,w] = sum_{c,kh,kw} wgen[b,o,c,kh,kw] * x[b,c,h+kh-1,w+kw-1] + bias[o]
// B=32, C=O=256, H=W=28, K=3, NUM=8.
// ---------------------------------------------------------------------------

#define BB   32
#define CIN  256
#define COUT 256
#define HH   28
#define WW   28

typedef unsigned long long ULL;

// Stage-1 output: weights pre-DUPLICATED as (w,w) ULLs, laid out exactly as the
// conv kernel's smem wants them:  [b][ob:16][k:32][cc:8][tap:9][o:16]  (151 MB)
__device__ ULL g_w2[(size_t)BB * 16 * 32 * 8 * 9 * 16];

__device__ __forceinline__ ULL pack2(float lo, float hi) {
    ULL r; asm("mov.b64 %0, {%1, %2};" : "=l"(r) : "f"(lo), "f"(hi)); return r;
}
__device__ __forceinline__ ULL ffma2(ULL a, ULL b, ULL c) {
    ULL d; asm("fma.rn.f32x2 %0, %1, %2, %3;" : "=l"(d) : "l"(a), "l"(b), "l"(c)); return d;
}
__device__ __forceinline__ ULL fadd2(ULL a, ULL b) {
    ULL d; asm("add.rn.f32x2 %0, %1, %2;" : "=l"(d) : "l"(a), "l"(b)); return d;
}
__device__ __forceinline__ float2 unpack2(ULL v) {
    float2 f; asm("mov.b64 {%0, %1}, %2;" : "=f"(f.x), "=f"(f.y) : "l"(v)); return f;
}
__device__ __forceinline__ void cp16(uint32_t dst, const void* src) {
    asm volatile("cp.async.ca.shared.global [%0], [%1], 16;\n"
                 :: "r"(dst), "l"(src) : "memory");
}
__device__ __forceinline__ void cp8(uint32_t dst, const void* src) {
    asm volatile("cp.async.ca.shared.global [%0], [%1], 8;\n"
                 :: "r"(dst), "l"(src) : "memory");
}
#define CP_COMMIT() asm volatile("cp.async.commit_group;\n" ::: "memory")
#define CP_WAIT0()  asm volatile("cp.async.wait_group 0;\n" ::: "memory")

// ---------------------------------------------------------------------------
// Stage 1: weight generation + duplication into the conv-ready layout.
// Thread owns one (o, c): reads its 72 bank floats once, loops 32 samples.
// Block 128 = 16 o_lo x 8 c_lo; grid 512 = 16 o_hi x 32 c_hi.
// ---------------------------------------------------------------------------
__global__ void wgen_kernel(const float* __restrict__ wbank,
                            const float* __restrict__ se) {
    __shared__ float s_se[BB * 8];
    int tid = threadIdx.x;                 // 0..127
    for (int i = tid; i < BB * 8; i += 128) s_se[i] = se[i];
    __syncthreads();

    const int o_lo = tid & 15, c_lo = tid >> 4;
    const int o_hi = blockIdx.x & 15, c_hi = blockIdx.x >> 4;
    const int o = o_hi * 16 + o_lo;
    const int c = c_hi * 8 + c_lo;

    const float4* src = (const float4*)wbank + (size_t)(o * CIN + c) * 18;
    float4 r[18];
    #pragma unroll
    for (int i = 0; i < 18; ++i) r[i] = src[i];

    for (int b = 0; b < BB; ++b) {
        const float* s = &s_se[b * 8];
        ULL* dst = g_w2 + ((((size_t)b * 16 + o_hi) * 32 + c_hi) * 8 + c_lo) * 144 + o_lo;
        #pragma unroll
        for (int t = 0; t < 9; ++t) {
            float4 a0 = r[2 * t], a1 = r[2 * t + 1];
            float v = a0.x * s[0];
            v = fmaf(a0.y, s[1], v);
            v = fmaf(a0.z, s[2], v);
            v = fmaf(a0.w, s[3], v);
            v = fmaf(a1.x, s[4], v);
            v = fmaf(a1.y, s[5], v);
            v = fmaf(a1.z, s[6], v);
            v = fmaf(a1.w, s[7], v);
            dst[t * 16] = pack2(v, v);
        }
    }
}

// ---------------------------------------------------------------------------
// Stage 2: direct conv. Block (16,14)=224 thr = 16 o-channels x 14 rows.
// Thread: 1 o x 1 row x 28 cols = 14 f32x2 accumulators.
// Input staged ONLY in natural alignment (padded rows of 32 floats:
//   f0,f1 = cols -2,-1 (zero), f2..f29 = cols 0..27, f30,f31 = zero).
// Shifted operand pairs are synthesized with pack2 on the ALU pipe.
// Weights arrive pre-duplicated; one conflict-free LDS.64 per tap.
// ---------------------------------------------------------------------------
#define CC   8               // channels per chunk
#define NR   16              // staged input rows (14 + 2 halo)
#define XROW 32              // floats per staged row
#define WCH  (8 * 9 * 16)    // 1152 ULLs of weights per chunk-block
#define XBUF (CC * NR * XROW)            // 4096 floats
#define SMEM_BYTES (2 * WCH * 8 + 2 * XBUF * 4)   // 18432 + 32768 = 51200

__global__ __launch_bounds__(224, 4)
void dconv_kernel(const float* __restrict__ x,
                  const float* __restrict__ bias,
                  float* __restrict__ out) {
    extern __shared__ ULL smem_u[];
    ULL*   ws = smem_u;                        // [2][1152] dup'd weights
    float* xs = (float*)(smem_u + 2 * WCH);    // [2][8][16][32] input rows

    const int tx  = threadIdx.x;       // 0..15 : o-lane
    const int ty  = threadIdx.y;       // 0..13 : output row
    const int tid = ty * 16 + tx;

    const int b       = blockIdx.y;
    const int ob      = blockIdx.x >> 1;   // 0..15
    const int rb      = blockIdx.x & 1;    // 0..1
    const int rowBase = rb * 14;

    const char*  wsrc = (const char*)(g_w2 + (((size_t)b * 16 + ob) * 32) * 1152);
    const float* xb   = x + (size_t)b * CIN * (HH * WW);

    const uint32_t ws_u = (uint32_t)__cvta_generic_to_shared(ws);
    const uint32_t xs_u = (uint32_t)__cvta_generic_to_shared(xs);

    // Zero input buffers once (pads + permanently-invalid halo rows stay 0).
    {
        float4* xz = (float4*)xs;
        for (int i = tid; i < (2 * XBUF) / 4; i += 224)
            xz[i] = make_float4(0.f, 0.f, 0.f, 0.f);
    }
    __syncthreads();

    // Per-thread fill coordinates: 224 = 16 rows x 14 col-pairs.
    const int fp   = tid % 14;             // col pair: cols (2fp, 2fp+1)
    const int frow = tid / 14;             // staged row 0..15
    const int fih  = rowBase - 1 + frow;
    const bool fvalid = (unsigned)fih < (unsigned)HH;
    const float* fsrc0 = xb + (size_t)fih * WW + 2 * fp;      // + cc*784
    const uint32_t fdst0 = xs_u + ((frow * XROW) + 2 + 2 * fp) * 4; // + cc*(XROW*4)

    ULL acc[14];
    #pragma unroll
    for (int j = 0; j < 14; ++j) acc[j] = 0ull;

    // ---- prologue: fill chunk 0 into buffer 0
    {
        #pragma unroll
        for (int i = 0; i < 3; ++i) {          // 576 cp16 over 224 threads
            int idx = tid + i * 224;
            if (idx < 576) cp16(ws_u + idx * 16, wsrc + idx * 16);
        }
        if (fvalid) {
            #pragma unroll
            for (int cc = 0; cc < CC; ++cc)
                cp8(fdst0 + cc * (NR * XROW * 4), fsrc0 + (size_t)cc * (HH * WW));
        }
        CP_COMMIT();
    }

    for (int k = 0; k < CIN / CC; ++k) {
        CP_WAIT0();
        __syncthreads();

        if (k < CIN / CC - 1) {
            const uint32_t wd = ws_u + ((k + 1) & 1) * (WCH * 8);
            const uint32_t xd = fdst0 + ((k + 1) & 1) * (XBUF * 4);
            const char* wsk = wsrc + (size_t)(k + 1) * (WCH * 8);
            #pragma unroll
            for (int i = 0; i < 3; ++i) {
                int idx = tid + i * 224;
                if (idx < 576) cp16(wd + idx * 16, wsk + idx * 16);
            }
            if (fvalid) {
                const float* fs = fsrc0 + (size_t)(k + 1) * CC * (HH * WW);
                #pragma unroll
                for (int cc = 0; cc < CC; ++cc)
                    cp8(xd + cc * (NR * XROW * 4), fs + (size_t)cc * (HH * WW));
            }
            CP_COMMIT();
        }

        const ULL*   wsb = ws + (k & 1) * WCH;
        const float* xsb = xs + (k & 1) * XBUF;

        for (int cc = 0; cc < CC; ++cc) {
            #pragma unroll
            for (int r = 0; r < 3; ++r) {
                // weights: 3 conflict-free broadcast LDS.64 (pre-duplicated)
                const ULL* wp = wsb + (cc * 9 + r * 3) * 16 + tx;
                ULL w0 = wp[0];
                ULL w1 = wp[16];
                ULL w2 = wp[32];
                // input row: float f = col + 2; P[p] = floats (2p, 2p+1)
                const float4* F = (const float4*)(xsb + (cc * NR + ty + r) * XROW);
                float4 f = F[0];                       // P[0], P[1]
                ULL O = pack2(f.y, f.z);               // O[0] = cols (-1, 0)
                #pragma unroll
                for (int t = 0; t < 7; ++t) {
                    float4 g = F[t + 1];               // P[2t+2], P[2t+3]
                    ULL tap1a = pack2(f.z, f.w);       // P[2t+1] (elided pack)
                    ULL Omid  = pack2(f.w, g.x);       // O[2t+1]
                    ULL tap1b = pack2(g.x, g.y);       // P[2t+2] (elided pack)
                    ULL Onext = pack2(g.y, g.z);       // O[2t+2]
                    acc[2*t]   = ffma2(w2, Omid,
                                 ffma2(w1, tap1a,
                                 ffma2(w0, O, acc[2*t])));
                    acc[2*t+1] = ffma2(w2, Onext,
                                 ffma2(w1, tap1b,
                                 ffma2(w0, Omid, acc[2*t+1])));
                    f = g; O = Onext;
                }
            }
        }
    }

    // ---- epilogue: bias + store
    const int o = ob * 16 + tx;
    const int h = rowBase + ty;
    float bv = bias[o];
    ULL bv2 = pack2(bv, bv);
    float2* op = (float2*)(out + (((size_t)b * COUT + o) * HH + h) * WW);
    #pragma unroll
    for (int j = 0; j < 14; ++j)
        op[j] = unpack2(fadd2(acc[j], bv2));
}

// ---------------------------------------------------------------------------
// Harness entry. Inputs (metadata order): inputs, inputs_se, weight, bias.
// ---------------------------------------------------------------------------
extern "C" void kernel_launch(void* const* d_in, const int* in_sizes, int n_in,
                              void* d_out, int out_size) {
    const float* x    = (const float*)d_in[0];   // [32,256,28,28]
    const float* se   = (const float*)d_in[1];   // [32,8]
    const float* wbk  = (const float*)d_in[2];   // [589824,8]
    const float* bias = (const float*)d_in[3];   // [256]
    float* out = (float*)d_out;                  // [32,256,28,28]

    cudaFuncSetAttribute(dconv_kernel,
                         cudaFuncAttributeMaxDynamicSharedMemorySize,
                         SMEM_BYTES);
    cudaFuncSetAttribute(dconv_kernel,
                         cudaFuncAttributePreferredSharedMemoryCarveout, 100);

    wgen_kernel<<<512, 128>>>(wbk, se);

    dim3 grid(32, BB);          // x: 16 o-blocks * 2 row-blocks, y: batch
    dim3 block(16, 14);         // 224 threads
    dconv_kernel<<<grid, block, SMEM_BYTES>>>(x, bias, out);
}

// round 11
// speedup vs baseline: 1.3159x; 1.3159x over previous
#include <cuda_runtime.h>
#include <cstdint>

// ---------------------------------------------------------------------------
// DiverseRegDCConv2d: per-sample dynamically-generated 3x3 conv.
//   wgen[b,o,c,kh,kw] = sum_n se[b,n] * weight[(o*C+c)*9+kh*3+kw, n]
//   out[b,o,h,w] = sum_{c,kh,kw} wgen[b,o,c,kh,kw] * x[b,c,h+kh-1,w+kw-1] + bias[o]
// B=32, C=O=256, H=W=28, K=3, NUM=8.
// ---------------------------------------------------------------------------

#define BB   32
#define CIN  256
#define COUT 256
#define HH   28
#define WW   28

typedef unsigned long long ULL;

// Stage-1 output: generated weights, o-major per tap for conflict-free LDS:
//   [b][ob:8][c:256][tap:9][o31:32]  (75.5 MB)
__device__ float g_wT[(size_t)BB * 8 * 256 * 9 * 32];
// Stage-0 output: input rows in dual alignment, cp16-ready (58.7 MB):
//   [b][c][h][64]: f0..27 = cols 0..27 | f28..31 = 0 | f32 = 0 (col -1) |
//                  f33..60 = cols 0..27 | f61..63 = 0
__device__ float g_xpad[(size_t)BB * CIN * HH * 64];

__device__ __forceinline__ ULL pack2(float lo, float hi) {
    ULL r; asm("mov.b64 %0, {%1, %2};" : "=l"(r) : "f"(lo), "f"(hi)); return r;
}
__device__ __forceinline__ ULL ffma2(ULL a, ULL b, ULL c) {
    ULL d; asm("fma.rn.f32x2 %0, %1, %2, %3;" : "=l"(d) : "l"(a), "l"(b), "l"(c)); return d;
}
__device__ __forceinline__ ULL fadd2(ULL a, ULL b) {
    ULL d; asm("add.rn.f32x2 %0, %1, %2;" : "=l"(d) : "l"(a), "l"(b)); return d;
}
__device__ __forceinline__ float2 unpack2(ULL v) {
    float2 f; asm("mov.b64 {%0, %1}, %2;" : "=f"(f.x), "=f"(f.y) : "l"(v)); return f;
}
__device__ __forceinline__ void cp16(uint32_t dst, const void* src) {
    asm volatile("cp.async.ca.shared.global [%0], [%1], 16;\n"
                 :: "r"(dst), "l"(src) : "memory");
}
#define CP_COMMIT() asm volatile("cp.async.commit_group;\n" ::: "memory")
#define CP_WAIT0()  asm volatile("cp.async.wait_group 0;\n" ::: "memory")

// ---------------------------------------------------------------------------
// Stage 0: build dual-aligned padded input rows (pure-cp16 conv fills).
// One thread per 16B output slot: 229376 rows x 16 slots.
// ---------------------------------------------------------------------------
__global__ void xpad_kernel(const float* __restrict__ x) {
    int gid = blockIdx.x * 256 + threadIdx.x;     // < 3,670,016
    int row = gid >> 4;                            // (b*256+c)*28+h
    int s   = gid & 15;
    const float* src = x + (size_t)row * WW;
    float4 v;
    if (s < 7) {
        v = *(const float4*)(src + 4 * s);         // cols 4s..4s+3 (aligned)
    } else if (s == 7) {
        v = make_float4(0.f, 0.f, 0.f, 0.f);
    } else {
        float t[4];
        #pragma unroll
        for (int m = 0; m < 4; ++m) {
            int col = 4 * s + m - 33;              // f = 4s+m, col = f-33
            t[m] = ((unsigned)col < (unsigned)WW) ? __ldg(src + col) : 0.f;
        }
        v = make_float4(t[0], t[1], t[2], t[3]);
    }
    *(float4*)(g_xpad + (size_t)row * 64 + 4 * s) = v;
}

// ---------------------------------------------------------------------------
// Stage 1: weight generation, written o-major per tap.
// Block = one (ob, c): 288 threads = 32 o31 x 9 taps; loops over 32 samples.
// Reads each bank row once; writes coalesced via smem transpose.
// ---------------------------------------------------------------------------
__global__ void wgen_kernel(const float* __restrict__ wbank,
                            const float* __restrict__ se) {
    __shared__ float s_se[BB * 8];
    __shared__ float sm[288];
    int tid = threadIdx.x;                 // 0..287
    if (tid < 256) s_se[tid] = se[tid];
    __syncthreads();

    const int c   = blockIdx.x & 255;
    const int ob  = blockIdx.x >> 8;       // 0..7
    const int o31 = tid / 9;
    const int t   = tid % 9;
    const int o   = ob * 32 + o31;

    const float4* src = (const float4*)wbank + ((size_t)(o * CIN + c) * 9 + t) * 2;
    float4 w0 = src[0];
    float4 w1 = src[1];

    float* dst0 = g_wT + (size_t)c * 288 + tid;
    for (int b = 0; b < BB; ++b) {
        const float* s = &s_se[b * 8];
        float v = w0.x * s[0];
        v = fmaf(w0.y, s[1], v);
        v = fmaf(w0.z, s[2], v);
        v = fmaf(w0.w, s[3], v);
        v = fmaf(w1.x, s[4], v);
        v = fmaf(w1.y, s[5], v);
        v = fmaf(w1.z, s[6], v);
        v = fmaf(w1.w, s[7], v);
        sm[t * 32 + o31] = v;
        __syncthreads();
        dst0[(size_t)(b * 8 + ob) * 256 * 288] = sm[tid];   // coalesced 288 floats
        __syncthreads();
    }
}

// ---------------------------------------------------------------------------
// Stage 2: direct conv. Block (16,14)=224 thr: 32 o-channels x 7 rows x 28 cols.
// Thread: 2 o-channels (tx, tx+16) x 1 row (ty>>1) x half-row (14 cols, ty&1).
// SMEM input row (72 floats, XR=72 -> conflict-free across rows):
//   A at f0..27 (col c @ f c), B at f36..67 (col c @ f 37+c; f36 = col -1 = 0)
//   Aq[j] = cols(2j,2j+1) [kw=1]; Bq[j] = cols(2j-1,2j) [kw=0]; Bq[j+1] [kw=2].
// Weights in smem o-major: [cc][tap][o:32] -> broadcast LDS.32, 1 wavefront.
// ---------------------------------------------------------------------------
#define CCK  4                       // channels per chunk (64 chunks)
#define NRW  9                       // staged rows (7 + 2 halo)
#define XR   72                      // floats per staged input row
#define XCH  (CCK * NRW * XR)        // 2592 floats per input buffer
#define WCH  (CCK * 9 * 32)          // 1152 floats per weight buffer
#define SMEM_BYTES ((2 * WCH + 2 * XCH) * 4)   // 9216 + 20736 = 29952 B

__global__ __launch_bounds__(224, 4)
void dconv_kernel(const float* __restrict__ bias,
                  float* __restrict__ out) {
    extern __shared__ float smem[];
    float* ws = smem;                // [2][WCH]
    float* xs = smem + 2 * WCH;      // [2][XCH]

    const int tx  = threadIdx.x;     // 0..15 : o-lane
    const int ty  = threadIdx.y;     // 0..13
    const int tid = ty * 16 + tx;
    const int row = ty >> 1;         // 0..6
    const int xh  = ty & 1;          // col half
    const int j0  = 7 * xh;

    const int b       = blockIdx.y;
    const int ob      = blockIdx.x >> 2;   // 0..7
    const int rb      = blockIdx.x & 3;    // 0..3
    const int oBase   = ob * 32;
    const int rowBase = rb * 7;

    const float* wsrc = g_wT + (size_t)(b * 8 + ob) * 256 * 288;  // + c*288
    const float* xsrc = g_xpad + (size_t)b * CIN * HH * 64;

    const uint32_t ws_u = (uint32_t)__cvta_generic_to_shared(ws);
    const uint32_t xs_u = (uint32_t)__cvta_generic_to_shared(xs);

    // Zero input buffers once (invalid halo rows stay zero forever).
    for (int i = tid; i < (2 * XCH) / 4; i += 224)
        ((float4*)xs)[i] = make_float4(0.f, 0.f, 0.f, 0.f);
    __syncthreads();

    ULL acc0[7], acc1[7];
    #pragma unroll
    for (int j = 0; j < 7; ++j) { acc0[j] = 0ull; acc1[j] = 0ull; }

    // ---- prologue: fill chunk 0 into buffer 0 (all cp16)
    {
        for (int i = tid; i < 288; i += 224)               // weights: 4608B
            cp16(ws_u + i * 16, wsrc + i * 4);
        for (int i = tid; i < 540; i += 224) {             // input: 15 cp16/row
            int cc = i / 135, rem = i % 135, rw = rem / 15, s = rem % 15;
            int ih = rowBase - 1 + rw;
            if ((unsigned)ih < (unsigned)HH) {
                int dco = (s < 7) ? s * 4 : 36 + (s - 7) * 4;
                int sco = (s < 7) ? s * 4 : 32 + (s - 7) * 4;
                cp16(xs_u + ((cc * NRW + rw) * XR + dco) * 4,
                     xsrc + ((size_t)cc * HH + ih) * 64 + sco);
            }
        }
        CP_COMMIT();
    }

    for (int k = 0; k < CIN / CCK; ++k) {
        CP_WAIT0();
        __syncthreads();

        if (k < CIN / CCK - 1) {
            const int c0 = (k + 1) * CCK;
            const uint32_t wd = ws_u + ((k + 1) & 1) * (WCH * 4);
            const uint32_t xd = xs_u + ((k + 1) & 1) * (XCH * 4);
            const float* wsk = wsrc + (size_t)c0 * 288;
            for (int i = tid; i < 288; i += 224)
                cp16(wd + i * 16, wsk + i * 4);
            for (int i = tid; i < 540; i += 224) {
                int cc = i / 135, rem = i % 135, rw = rem / 15, s = rem % 15;
                int ih = rowBase - 1 + rw;
                if ((unsigned)ih < (unsigned)HH) {
                    int dco = (s < 7) ? s * 4 : 36 + (s - 7) * 4;
                    int sco = (s < 7) ? s * 4 : 32 + (s - 7) * 4;
                    cp16(xd + ((cc * NRW + rw) * XR + dco) * 4,
                         xsrc + ((size_t)(c0 + cc) * HH + ih) * 64 + sco);
                }
            }
            CP_COMMIT();
        }

        const float* wsb = ws + (k & 1) * WCH;
        const float* xsb = xs + (k & 1) * XCH;

        #pragma unroll
        for (int cc = 0; cc < CCK; ++cc) {
            #pragma unroll
            for (int r = 0; r < 3; ++r) {
                const float* wp = wsb + (cc * 9 + r * 3) * 32;
                float a0 = wp[tx],      c0f = wp[tx + 16];       // kw=0
                float a1 = wp[32 + tx], c1f = wp[48 + tx];       // kw=1
                float a2 = wp[64 + tx], c2f = wp[80 + tx];       // kw=2
                ULL wA0 = pack2(a0, a0), wB0 = pack2(c0f, c0f);
                ULL wA1 = pack2(a1, a1), wB1 = pack2(c1f, c1f);
                ULL wA2 = pack2(a2, a2), wB2 = pack2(c2f, c2f);
                const float* xr = xsb + (cc * NRW + row + r) * XR;
                const ULL* Aq = (const ULL*)xr;
                const ULL* Bq = (const ULL*)(xr + 36);
                ULL b0 = Bq[j0];
                #pragma unroll
                for (int jj = 0; jj < 7; ++jj) {
                    ULL a  = Aq[j0 + jj];
                    ULL b1 = Bq[j0 + jj + 1];
                    acc0[jj] = ffma2(wA2, b1,
                               ffma2(wA1, a,
                               ffma2(wA0, b0, acc0[jj])));
                    acc1[jj] = ffma2(wB2, b1,
                               ffma2(wB1, a,
                               ffma2(wB0, b0, acc1[jj])));
                    b0 = b1;
                }
            }
        }
    }

    // ---- epilogue: bias + store (2 o x 7 float2 each)
    const int o0 = oBase + tx, o1 = o0 + 16;
    const int h  = rowBase + row;
    float bv0 = bias[o0], bv1 = bias[o1];
    ULL bb0 = pack2(bv0, bv0), bb1 = pack2(bv1, bv1);
    float2* p0 = (float2*)(out + (((size_t)b * COUT + o0) * HH + h) * WW + 2 * j0);
    float2* p1 = (float2*)(out + (((size_t)b * COUT + o1) * HH + h) * WW + 2 * j0);
    #pragma unroll
    for (int jj = 0; jj < 7; ++jj) {
        p0[jj] = unpack2(fadd2(acc0[jj], bb0));
        p1[jj] = unpack2(fadd2(acc1[jj], bb1));
    }
}

// ---------------------------------------------------------------------------
// Harness entry. Inputs (metadata order): inputs, inputs_se, weight, bias.
// ---------------------------------------------------------------------------
extern "C" void kernel_launch(void* const* d_in, const int* in_sizes, int n_in,
                              void* d_out, int out_size) {
    const float* x    = (const float*)d_in[0];   // [32,256,28,28]
    const float* se   = (const float*)d_in[1];   // [32,8]
    const float* wbk  = (const float*)d_in[2];   // [589824,8]
    const float* bias = (const float*)d_in[3];   // [256]
    float* out = (float*)d_out;                  // [32,256,28,28]

    cudaFuncSetAttribute(dconv_kernel,
                         cudaFuncAttributePreferredSharedMemoryCarveout, 100);

    xpad_kernel<<<(BB * CIN * HH * 16) / 256, 256>>>(x);   // 14336 blocks
    wgen_kernel<<<8 * 256, 288>>>(wbk, se);                // 2048 blocks

    dim3 grid(32, BB);          // x: 8 o-blocks * 4 row-blocks, y: batch
    dim3 block(16, 14);         // 224 threads
    dconv_kernel<<<grid, block, SMEM_BYTES>>>(bias, out);
}